// round 17
// baseline (speedup 1.0000x reference)
#include <cuda_runtime.h>
#include <cuda_fp16.h>
#include <cstdint>

#define NN   12288
#define KK   32
#define DD   128

typedef unsigned long long ull;

// Scratch: G = raw_features @ W_lin^T, fp16 (N x 128, 3.15 MB)
__device__ __align__(16) __half g_Gh[NN * DD];

// ---------------------------------------------------------------------------
// helpers
// ---------------------------------------------------------------------------
__device__ __forceinline__ ull pack_dup(float x) {
    ull r;
    asm("mov.b64 %0, {%1, %1};" : "=l"(r) : "f"(x));
    return r;
}
__device__ __forceinline__ void fma2(ull& d, ull a, ull b) {
    asm("fma.rn.f32x2 %0, %1, %2, %0;" : "+l"(d) : "l"(a), "l"(b));
}
__device__ __forceinline__ void unpack2(float& lo, float& hi, ull v) {
    asm("mov.b64 {%0, %1}, %2;" : "=f"(lo), "=f"(hi) : "l"(v));
}
__device__ __forceinline__ unsigned smem_u32(const void* p) {
    unsigned r;
    asm("{ .reg .u64 t; cvta.to.shared.u64 t, %1; cvt.u32.u64 %0, t; }"
        : "=r"(r) : "l"(p));
    return r;
}

// ---------------------------------------------------------------------------
// Kernel 1: G = F @ W^T via HMMA (mma.sync.m16n8k16, f16 in / f32 acc,
// fp16 out). v3: 192 CTAs x 64 M-rows x 256 thr — all 148 SMs active,
// 2 CTAs co-resident on 44 SMs (smem 52KB) so staging overlaps compute.
// Warps: wM = wid&3 -> rows 16*wM..+15;  wN = wid>>2 -> cols 64*wN..+63.
//   Ah [64][136]  fp16 A rows      (pad 136: ldmatrix conflict-free)
//   Bh [128][136] fp16 W transposed: Bh[k][n] = W[n][k]
// ---------------------------------------------------------------------------
__global__ void __launch_bounds__(256)
gemm_hmma_kernel(const float* __restrict__ F, const float* __restrict__ W)
{
    extern __shared__ __half sh[];
    __half* Ah = sh;                  // [64][136]
    __half* Bh = sh + 64 * 136;       // [128][136]

    const int tid = threadIdx.x;
    const int bm  = blockIdx.x;
    const float* Fblk = F + (size_t)bm * 64 * DD;

    // ---- stage A: 64x128 f32 -> f16 (8 float4 per thread) ----
    #pragma unroll
    for (int i = 0; i < 8; i++) {
        const int flat = (tid + i * 256) * 4;
        const int r = flat >> 7, c = flat & 127;
        const float4 v = *reinterpret_cast<const float4*>(&Fblk[flat]);
        __half2 h0 = __floats2half2_rn(v.x, v.y);
        __half2 h1 = __floats2half2_rn(v.z, v.w);
        uint2 st;
        st.x = *reinterpret_cast<unsigned*>(&h0);
        st.y = *reinterpret_cast<unsigned*>(&h1);
        *reinterpret_cast<uint2*>(&Ah[r * 136 + c]) = st;
    }
    // ---- stage B transposed: Bh[k][n] = W[n][k] ----
    #pragma unroll
    for (int i = 0; i < 16; i++) {
        const int flat = (tid + i * 256) * 4;
        const int n = flat >> 7, k = flat & 127;
        const float4 v = *reinterpret_cast<const float4*>(&W[flat]);
        Bh[(k + 0) * 136 + n] = __float2half_rn(v.x);
        Bh[(k + 1) * 136 + n] = __float2half_rn(v.y);
        Bh[(k + 2) * 136 + n] = __float2half_rn(v.z);
        Bh[(k + 3) * 136 + n] = __float2half_rn(v.w);
    }
    __syncthreads();

    const int wid  = tid >> 5;
    const int lane = tid & 31;
    const int m0   = (wid & 3) << 4;       // 0,16,32,48
    const int n0   = (wid >> 2) << 6;      // 0,64

    float acc[8][4];
    #pragma unroll
    for (int j = 0; j < 8; j++)
        #pragma unroll
        for (int t = 0; t < 4; t++)
            acc[j][t] = 0.0f;

    const unsigned aAddr0 = smem_u32(Ah);
    const unsigned bAddr0 = smem_u32(Bh);
    const int l15 = lane & 15;

    #pragma unroll
    for (int kc = 0; kc < 8; kc++) {
        const int k0 = kc * 16;
        unsigned pa = aAddr0 +
            ((m0 + l15) * 136 + k0 + ((lane >> 4) << 3)) * 2;
        unsigned a0, a1, a2, a3;
        asm volatile("ldmatrix.sync.aligned.m8n8.x4.shared.b16 {%0,%1,%2,%3}, [%4];"
                     : "=r"(a0), "=r"(a1), "=r"(a2), "=r"(a3) : "r"(pa));

        #pragma unroll
        for (int j = 0; j < 8; j++) {
            unsigned pb = bAddr0 + ((k0 + l15) * 136 + n0 + 8 * j) * 2;
            unsigned b0, b1;
            asm volatile("ldmatrix.sync.aligned.m8n8.x2.trans.shared.b16 {%0,%1}, [%2];"
                         : "=r"(b0), "=r"(b1) : "r"(pb));
            asm volatile(
                "mma.sync.aligned.m16n8k16.row.col.f32.f16.f16.f32 "
                "{%0,%1,%2,%3}, {%4,%5,%6,%7}, {%8,%9}, {%0,%1,%2,%3};"
                : "+f"(acc[j][0]), "+f"(acc[j][1]),
                  "+f"(acc[j][2]), "+f"(acc[j][3])
                : "r"(a0), "r"(a1), "r"(a2), "r"(a3), "r"(b0), "r"(b1));
        }
    }

    // ---- epilogue: D frags -> fp16 G ----
    const int grow = bm * 64 + m0 + (lane >> 2);
    const int coff = n0 + (lane & 3) * 2;
    #pragma unroll
    for (int j = 0; j < 8; j++) {
        __half2 lo = __floats2half2_rn(acc[j][0], acc[j][1]);
        __half2 hi = __floats2half2_rn(acc[j][2], acc[j][3]);
        *reinterpret_cast<__half2*>(&g_Gh[(size_t)grow * DD + 8 * j + coff]) = lo;
        *reinterpret_cast<__half2*>(&g_Gh[(size_t)(grow + 8) * DD + 8 * j + coff]) = hi;
    }
}

// ---------------------------------------------------------------------------
// Kernel 2 (fused, R14-proven): w-prep prologue + gather.
// 768 blocks x 256 thr = 16 nodes/block. Prologue: 2 random rew loads per
// thread (batched); body: warp = 2 nodes, lane owns 8 fp16 cols (LDG.128),
// packed f32x2 accumulate.
// ---------------------------------------------------------------------------
__global__ void __launch_bounds__(256)
gather_fused_kernel(const int* __restrict__ nodes,
                    const int* __restrict__ neighbors,
                    const float* __restrict__ rew,
                    const float* __restrict__ b_lin,
                    float* __restrict__ out)
{
    __shared__ int   nb_s[16][KK];
    __shared__ float w_s [16][KK];

    const int tid = threadIdx.x;
    const int b0  = blockIdx.x * 16;

    {
        const int e0 = tid, e1 = tid + 256;
        const int b_a = b0 + (e0 >> 5), k_a = e0 & 31;
        const int b_b = b0 + (e1 >> 5), k_b = e1 & 31;
        const int nd_a = __ldg(&nodes[b_a]);
        const int nd_b = __ldg(&nodes[b_b]);
        const int nb_a = __ldg(&neighbors[b_a * KK + k_a]);
        const int nb_b = __ldg(&neighbors[b_b * KK + k_b]);
        float w_a = 0.0f, w_b = 0.0f;
        if (nb_a != nd_a) w_a = __ldg(&rew[(size_t)nd_a * NN + nb_a]);
        if (nb_b != nd_b) w_b = __ldg(&rew[(size_t)nd_b * NN + nb_b]);
        nb_s[e0 >> 5][k_a] = nb_a;  w_s[e0 >> 5][k_a] = w_a;
        nb_s[e1 >> 5][k_b] = nb_b;  w_s[e1 >> 5][k_b] = w_b;
    }
    __syncthreads();

    const int lane = tid & 31;
    const int ln2  = ((tid >> 5) << 1) | (lane >> 4);  // local node 0..15
    const int col  = (lane & 15) * 8;                  // 8 cols per lane
    const int b    = b0 + ln2;

    ull acc[4];
    #pragma unroll
    for (int i = 0; i < 4; i++) acc[i] = 0ULL;

    #pragma unroll
    for (int kb = 0; kb < KK; kb += 4) {
        uint4 g[4];
        float wv[4];
        #pragma unroll
        for (int u = 0; u < 4; u++) {
            const int nb = nb_s[ln2][kb + u];
            wv[u] = w_s[ln2][kb + u];
            g[u]  = __ldg(reinterpret_cast<const uint4*>(
                              &g_Gh[(size_t)nb * DD + col]));
        }
        #pragma unroll
        for (int u = 0; u < 4; u++) {
            const ull wd = pack_dup(wv[u]);
            float2 f0 = __half22float2(*reinterpret_cast<__half2*>(&g[u].x));
            float2 f1 = __half22float2(*reinterpret_cast<__half2*>(&g[u].y));
            float2 f2 = __half22float2(*reinterpret_cast<__half2*>(&g[u].z));
            float2 f3 = __half22float2(*reinterpret_cast<__half2*>(&g[u].w));
            fma2(acc[0], wd, *reinterpret_cast<ull*>(&f0));
            fma2(acc[1], wd, *reinterpret_cast<ull*>(&f1));
            fma2(acc[2], wd, *reinterpret_cast<ull*>(&f2));
            fma2(acc[3], wd, *reinterpret_cast<ull*>(&f3));
        }
    }

    float a[8];
    #pragma unroll
    for (int i = 0; i < 4; i++) unpack2(a[2 * i], a[2 * i + 1], acc[i]);

    const float4 bias0 = __ldg(reinterpret_cast<const float4*>(&b_lin[col]));
    const float4 bias1 = __ldg(reinterpret_cast<const float4*>(&b_lin[col + 4]));
    float4 o0, o1;
    o0.x = fmaxf(a[0] + bias0.x, 0.f);
    o0.y = fmaxf(a[1] + bias0.y, 0.f);
    o0.z = fmaxf(a[2] + bias0.z, 0.f);
    o0.w = fmaxf(a[3] + bias0.w, 0.f);
    o1.x = fmaxf(a[4] + bias1.x, 0.f);
    o1.y = fmaxf(a[5] + bias1.y, 0.f);
    o1.z = fmaxf(a[6] + bias1.z, 0.f);
    o1.w = fmaxf(a[7] + bias1.w, 0.f);
    float* op = &out[(size_t)b * DD + col];
    *reinterpret_cast<float4*>(op)     = o0;
    *reinterpret_cast<float4*>(op + 4) = o1;
}

// ---------------------------------------------------------------------------
// Launch: serial, 2 kernels (R14 structure; overlap + cache hints proven
// harmful in R9/11/12/13/15/16).
// Inputs: nodes(i32 N), neighbors(i32 N*K), raw_features(f32 N*128),
//         reweighted(f32 N*N), W_lin(f32 128*128), b_lin(f32 128)
// ---------------------------------------------------------------------------
extern "C" void kernel_launch(void* const* d_in, const int* in_sizes, int n_in,
                              void* d_out, int out_size)
{
    const int*   nodes      = (const int*)  d_in[0];
    const int*   neighbors  = (const int*)  d_in[1];
    const float* raw_feats  = (const float*)d_in[2];
    const float* reweighted = (const float*)d_in[3];
    const float* W_lin      = (const float*)d_in[4];
    const float* b_lin      = (const float*)d_in[5];
    float*       out        = (float*)d_out;

    const int smem = (64 + 128) * 136 * (int)sizeof(__half);  // 52224 B
    static bool attr_set = false;
    if (!attr_set) {
        cudaFuncSetAttribute(gemm_hmma_kernel,
                             cudaFuncAttributeMaxDynamicSharedMemorySize, smem);
        attr_set = true;
    }

    gemm_hmma_kernel<<<NN / 64, 256, smem>>>(raw_feats, W_lin);
    gather_fused_kernel<<<NN / 16, 256>>>(nodes, neighbors, reweighted,
                                          b_lin, out);
}